// round 17
// baseline (speedup 1.0000x reference)
#include <cuda_runtime.h>
#include <cstdint>

// HairBundle SDE drift + constant diffusion. Streaming, memory-bound.
// Floor: 480MB (160R+320W). R10/R12 best: 73.95us total / 67.2-67.4 kernel /
// DRAM 78.8% across all structures (occ 56-90%) -> suspected HBM r/w-mix wall,
// last SM-side suspect = L1tex 54% (160 LDGSTS per warp on the read path).
// R13: reads ALSO via bulk DMA: one 2560B cp.async.bulk G2S + mbarrier per
// warp. Both directions on the async engine; SM only computes.

#define TPB 256
#define WPB (TPB / 32)
#define F4T 160                      // float4 per warp-tile = 128 rows
#define TILE_BYTES (F4T * 16)        // 2560

__device__ __forceinline__ void hb_row(float x_hb, float x_a, float p_m,
                                       float p_gs, float p_t, float force,
                                       float* __restrict__ o) {
    float z    = 4.0f * (x_hb - x_a);                 // (x_hb - x_a)/DELTA
    float p_o  = 1.0f / (1.0f + __expf(-z));          // sigmoid
    float f_gs = 0.75f * (x_hb - x_a - 0.5f * p_o);
    o[0] = -f_gs - 0.6f * x_hb + force;
    o[1] = 0.1f * (f_gs - 0.45f * x_a - 0.35f * (1.0f - 0.9f * p_m));
    o[2] = 1.2f * p_o * (1.0f - p_m)  - 0.8f * p_m;
    o[3] = 0.7f * p_o * (1.0f - p_gs) - 0.5f * p_gs;
    o[4] = 0.3f * p_o * (1.0f - p_t)  - 0.4f * p_t;
}

__device__ __forceinline__ void bulk_s2g(void* gptr, uint32_t smem_addr,
                                         uint32_t bytes) {
    asm volatile("cp.async.bulk.global.shared::cta.bulk_group [%0], [%1], %2;\n"
                 :: "l"(gptr), "r"(smem_addr), "r"(bytes) : "memory");
}

__device__ __forceinline__ void bulk_g2s(uint32_t smem_addr, const void* gptr,
                                         uint32_t bytes, uint32_t mbar_addr) {
    asm volatile(
        "cp.async.bulk.shared::cluster.global.mbarrier::complete_tx::bytes "
        "[%0], [%1], %2, [%3];\n"
        :: "r"(smem_addr), "l"(gptr), "r"(bytes), "r"(mbar_addr) : "memory");
}

__global__ __launch_bounds__(TPB, 8)
void hb_kernel(const float* __restrict__ t,
               const float4* __restrict__ x4,
               float4* __restrict__ drift4,
               float4* __restrict__ diffu4,
               int nf4, int B) {
    __shared__ float4 buf[WPB][F4T];     // 20KB: in-place input->drift slabs
    __shared__ float4 slab[F4T];         // 2.5KB: constant diffusion tile
    __shared__ uint64_t mbar[WPB];       // one mbarrier per warp
    const int tid  = threadIdx.x;
    const int lane = tid & 31;
    const int w    = tid >> 5;
    const int wid  = blockIdx.x * WPB + w;            // global warp id
    const int base = wid * F4T;                        // f4 offset (fits int)
    const bool full = (base + F4T <= nf4);

    uint32_t sbase = (uint32_t)__cvta_generic_to_shared(&buf[w][0]);
    uint32_t mb    = (uint32_t)__cvta_generic_to_shared(&mbar[w]);

    // ---- lane 0: init mbarrier, then launch the 2560B bulk read ----
    if (full && lane == 0) {
        asm volatile("mbarrier.init.shared.b64 [%0], 1;\n" :: "r"(mb) : "memory");
        asm volatile("fence.proxy.async.shared::cta;\n" ::: "memory");
        asm volatile("mbarrier.arrive.expect_tx.shared.b64 _, [%0], %1;\n"
                     :: "r"(mb), "r"((uint32_t)TILE_BYTES) : "memory");
        bulk_g2s(sbase, x4 + base, TILE_BYTES, mb);
    }

    // ---- diffusion slab: period-5 f4 pattern; every tile base % 5 == 0 ----
    if (tid < F4T) {
        int p = tid % 5;
        slab[tid] = (p == 0) ? make_float4(0.05f, 0.02f, 0.0f,  0.0f)  :
                    (p == 1) ? make_float4(0.0f,  0.05f, 0.02f, 0.0f)  :
                    (p == 2) ? make_float4(0.0f,  0.0f,  0.05f, 0.02f) :
                    (p == 3) ? make_float4(0.0f,  0.0f,  0.0f,  0.05f) :
                               make_float4(0.02f, 0.0f,  0.0f,  0.0f);
    }
    __syncthreads();   // slab + mbarrier inits visible block-wide

    const float force = 0.5f * __sinf(6.283185307179586f * t[0]);

    if (full) {
        // ---- diffusion bulk-store: write burst in flight during read wait ----
        if (lane == 0) {
            asm volatile("fence.proxy.async.shared::cta;\n" ::: "memory");
            uint32_t sslab = (uint32_t)__cvta_generic_to_shared(&slab[0]);
            bulk_s2g(diffu4 + base, sslab, TILE_BYTES);
            asm volatile("cp.async.bulk.commit_group;\n" ::: "memory");
        }

        // ---- all lanes: wait for the bulk read (parity 0, acquire) ----
        {
            uint32_t done;
            asm volatile(
                "{\n\t.reg .pred p;\n\t"
                "mbarrier.try_wait.parity.acquire.cta.shared::cta.b64 p, [%1], 0;\n\t"
                "selp.b32 %0, 1, 0, p;\n\t}"
                : "=r"(done) : "r"(mb) : "memory");
            while (!done) {
                asm volatile(
                    "{\n\t.reg .pred p;\n\t"
                    "mbarrier.try_wait.parity.acquire.cta.shared::cta.b64 p, [%1], 0, 0x989680;\n\t"
                    "selp.b32 %0, 1, 0, p;\n\t}"
                    : "=r"(done) : "r"(mb) : "memory");
            }
        }
        __syncwarp();

        // ---- compute 4 rows in place (lane slice i5 = lane*5) ----
        {
            const int i5 = lane * 5;
            float4 a = buf[w][i5 + 0];
            float4 b = buf[w][i5 + 1];
            float o0[5], o1[5];
            hb_row(a.x, a.y, a.z, a.w, b.x, force, o0);       // row 0
            float4 c = buf[w][i5 + 2];
            hb_row(b.y, b.z, b.w, c.x, c.y, force, o1);       // row 1
            buf[w][i5 + 0] = make_float4(o0[0], o0[1], o0[2], o0[3]);
            buf[w][i5 + 1] = make_float4(o0[4], o1[0], o1[1], o1[2]);
            float4 d = buf[w][i5 + 3];
            float o2[5];
            hb_row(c.z, c.w, d.x, d.y, d.z, force, o2);       // row 2
            buf[w][i5 + 2] = make_float4(o1[3], o1[4], o2[0], o2[1]);
            float4 e = buf[w][i5 + 4];
            float o3[5];
            hb_row(d.w, e.x, e.y, e.z, e.w, force, o3);       // row 3
            buf[w][i5 + 3] = make_float4(o2[2], o2[3], o2[4], o3[0]);
            buf[w][i5 + 4] = make_float4(o3[1], o3[2], o3[3], o3[4]);
        }
        __syncwarp();   // all lanes' smem writes done before bulk issue

        if (lane == 0) {
            asm volatile("fence.proxy.async.shared::cta;\n" ::: "memory");
            bulk_s2g(drift4 + base, sbase, TILE_BYTES);
            asm volatile("cp.async.bulk.commit_group;\n" ::: "memory");
            asm volatile("cp.async.bulk.wait_group 0;\n" ::: "memory");
        }
    } else {
        // ---- partial warp: scalar per-row fallback (empty for B=8M) ----
        const float* xs = (const float*)x4;
        float* drs = (float*)drift4;
        float* dfs = (float*)diffu4;
        int row0 = wid * 128;                 // 160 f4 = 128 rows per warp
        for (int r = row0 + lane; r < B; r += 32) {
            const float* xr = xs + (size_t)r * 5;
            float o[5];
            hb_row(xr[0], xr[1], xr[2], xr[3], xr[4], force, o);
            float* dr = drs + (size_t)r * 5;
            float* gr = dfs + (size_t)r * 5;
            dr[0] = o[0]; dr[1] = o[1]; dr[2] = o[2]; dr[3] = o[3]; dr[4] = o[4];
            gr[0] = 0.05f; gr[1] = 0.02f; gr[2] = 0.0f; gr[3] = 0.0f; gr[4] = 0.0f;
        }
    }
}

extern "C" void kernel_launch(void* const* d_in, const int* in_sizes, int n_in,
                              void* d_out, int out_size) {
    const float* t  = (const float*)d_in[0];   // [1]
    const float* x  = (const float*)d_in[1];   // [B*5]
    float* out      = (float*)d_out;
    int B           = in_sizes[1] / 5;
    int nf4         = in_sizes[1] / 4;         // B*5 % 4 == 0 for B=8M
    float* drift    = out;
    float* diffu    = out + (size_t)out_size / 2;

    int nwarps  = (B + 127) / 128;             // 62500 for B=8M
    int nblocks = (nwarps + WPB - 1) / WPB;    // 7813

    hb_kernel<<<nblocks, TPB>>>(t, (const float4*)x,
                                (float4*)drift, (float4*)diffu, nf4, B);
}